// round 9
// baseline (speedup 1.0000x reference)
#include <cuda_runtime.h>
#include <cuda_bf16.h>
#include <cstdint>

#define B_   4
#define V_   256
#define H_   128
#define KE_  32
#define H2_  256
#define ST_W 136
#define ST_E2 40
#define NBI  (B_*V_)
#define ETILE 10240
#define EBYTES 20480

__device__ float g_P [NBI*H_];
__device__ float g_Q [NBI*H_];
__device__ float g_X1[NBI*H_];
__device__ float g_X2[NBI*H_];
__device__ float g_R [NBI*H2_];
__device__ float g_S [NBI*H2_];
__device__ __align__(16) unsigned short g_w1hi[2][KE_*ST_W];
__device__ __align__(16) unsigned short g_w1lo[2][KE_*ST_W];
__device__ __align__(16) unsigned short g_w2hi[2][H_*ST_W];
__device__ __align__(16) unsigned short g_w2lo[2][H_*ST_W];
__device__ __align__(16) unsigned short g_Ehi[NBI][ETILE];
__device__ __align__(16) unsigned short g_Elo[NBI][ETILE];

__device__ __forceinline__ unsigned short bf16b(float f) {
    __nv_bfloat16 h = __float2bfloat16(f);
    return *(unsigned short*)&h;
}
__device__ __forceinline__ float bf16f(unsigned short u) {
    __nv_bfloat16 h = *(__nv_bfloat16*)&u;
    return __bfloat162float(h);
}
__device__ __forceinline__ uint32_t smem_to_u32(const void* p) {
    uint32_t a;
    asm("{ .reg .u64 t; cvta.to.shared.u64 t, %1; cvt.u32.u64 %0, t; }" : "=r"(a) : "l"(p));
    return a;
}
__device__ __forceinline__ void ldsm4(uint32_t* r, uint32_t a) {
    asm volatile("ldmatrix.sync.aligned.m8n8.x4.shared.b16 {%0,%1,%2,%3}, [%4];"
        : "=r"(r[0]), "=r"(r[1]), "=r"(r[2]), "=r"(r[3]) : "r"(a));
}
__device__ __forceinline__ void ldsm4t(uint32_t* r, uint32_t a) {
    asm volatile("ldmatrix.sync.aligned.m8n8.x4.trans.shared.b16 {%0,%1,%2,%3}, [%4];"
        : "=r"(r[0]), "=r"(r[1]), "=r"(r[2]), "=r"(r[3]) : "r"(a));
}
__device__ __forceinline__ void mma_bf16(float* c, const uint32_t* a, const uint32_t* b) {
    asm volatile("mma.sync.aligned.m16n8k16.row.col.f32.bf16.bf16.f32 "
        "{%0,%1,%2,%3}, {%4,%5,%6,%7}, {%8,%9}, {%0,%1,%2,%3};"
        : "+f"(c[0]), "+f"(c[1]), "+f"(c[2]), "+f"(c[3])
        : "r"(a[0]), "r"(a[1]), "r"(a[2]), "r"(a[3]), "r"(b[0]), "r"(b[1]));
}
__device__ __forceinline__ void cp16(uint32_t dst, const void* src) {
    asm volatile("cp.async.cg.shared.global [%0], [%1], 16;" :: "r"(dst), "l"(src));
}
#define CP_COMMIT() asm volatile("cp.async.commit_group;" ::: "memory")
#define CP_WAIT1()  asm volatile("cp.async.wait_group 1;" ::: "memory")
#define CP_WAIT0()  asm volatile("cp.async.wait_group 0;" ::: "memory")

// SMEM byte offsets (ec kernel)
#define OFF_B2    0
#define OFF_P     512
#define OFF_ADJ   1024
#define OFF_RED   2048
#define OFF_W1HI  6144
#define OFF_W1LO  14848
#define OFF_W2HI  23552
#define OFF_W2LO  58368
#define OFF_E0    93184
#define EBUF_SZ   (2*EBYTES)
#define OFF_TLO   (OFF_E0 + 2*EBUF_SZ)       // 175104: Tlo fragments 32KB
#define SMEM_EC   (OFF_TLO + 32768)          // 207872

// ---------------------------------------------------------------------------
__device__ __forceinline__ void pq_impl(int group, const float* __restrict__ x,
                                        const float* __restrict__ W1,
                                        const float* __restrict__ b1, int C_in,
                                        float* __restrict__ P, float* __restrict__ Q)
{
    __shared__ float sx[4][128];
    __shared__ float sp[2][4][128], sq[2][4][128];
    const int tid = threadIdx.x;
    const int cs = tid >> 7, h = tid & 127;
    const int base = group * 4;
    const int lg = (C_in == 64) ? 6 : 7;
    for (int i = tid; i < 4*C_in; i += 256)
        sx[i >> lg][i & (C_in-1)] = x[(size_t)(base + (i >> lg))*C_in + (i & (C_in-1))];
    __syncthreads();

    const int c0 = cs * (C_in >> 1), c1 = c0 + (C_in >> 1);
    float p[4] = {0.f,0.f,0.f,0.f}, q[4] = {0.f,0.f,0.f,0.f};
    for (int c = c0; c < c1; ++c) {
        float wa = W1[c*H_ + h], wb = W1[(C_in+c)*H_ + h], wd = wa - wb;
        #pragma unroll
        for (int r = 0; r < 4; ++r) { p[r] += sx[r][c]*wd; q[r] += sx[r][c]*wb; }
    }
    #pragma unroll
    for (int r = 0; r < 4; ++r) { sp[cs][r][h] = p[r]; sq[cs][r][h] = q[r]; }
    __syncthreads();
    if (cs == 0) {
        float bb = b1[h];
        #pragma unroll
        for (int r = 0; r < 4; ++r) {
            P[(size_t)(base+r)*H_ + h] = sp[0][r][h] + sp[1][r][h] + bb;
            Q[(size_t)(base+r)*H_ + h] = sq[0][r][h] + sq[1][r][h];
        }
    }
}

__global__ void prep_all(const float* __restrict__ E,
                         const float* __restrict__ W1a, const float* __restrict__ W2a,
                         const float* __restrict__ W1b, const float* __restrict__ W2b,
                         const float* __restrict__ x0,  const float* __restrict__ b1a,
                         float* __restrict__ P, float* __restrict__ Q)
{
    const int blk = blockIdx.x, tid = threadIdx.x;
    if (blk < NBI) {
        unsigned short* eh = g_Ehi[blk];
        unsigned short* el = g_Elo[blk];
        for (int idx = tid; idx < 2048; idx += 256) {
            int j = idx >> 3, kq = idx & 7;
            float4 e4 = *(const float4*)(E + ((size_t)blk*V_ + j)*KE_ + kq*4);
            unsigned short h0=bf16b(e4.x), h1=bf16b(e4.y), h2=bf16b(e4.z), h3=bf16b(e4.w);
            uint2 hp, lp;
            hp.x = (uint32_t)h0 | ((uint32_t)h1 << 16);
            hp.y = (uint32_t)h2 | ((uint32_t)h3 << 16);
            lp.x = (uint32_t)bf16b(e4.x-bf16f(h0)) | ((uint32_t)bf16b(e4.y-bf16f(h1)) << 16);
            lp.y = (uint32_t)bf16b(e4.z-bf16f(h2)) | ((uint32_t)bf16b(e4.w-bf16f(h3)) << 16);
            int o = j*ST_E2 + kq*4;
            *(uint2*)(eh + o) = hp;
            *(uint2*)(el + o) = lp;
        }
    } else if (blk < NBI + 160) {
        int idx = (blk - NBI) * 256 + tid;
        if (idx < 40960) {
            int layer = idx / 20480;
            int t = idx - layer * 20480;
            const float* W1 = layer ? W1b : W1a;
            const float* W2 = layer ? W2b : W2a;
            const int C = layer ? 128 : 64;
            if (t < KE_*H_) {
                int k = t >> 7, c = t & 127;
                float w = W1[(size_t)(2*C + k)*H_ + c];
                unsigned short h = bf16b(w);
                g_w1hi[layer][k*ST_W + c] = h;
                g_w1lo[layer][k*ST_W + c] = bf16b(w - bf16f(h));
            } else {
                int t2 = t - KE_*H_;
                int k = t2 >> 7, c = t2 & 127;
                float w = W2[(size_t)k*H_ + c];
                unsigned short h = bf16b(w);
                g_w2hi[layer][k*ST_W + c] = h;
                g_w2lo[layer][k*ST_W + c] = bf16b(w - bf16f(h));
            }
        }
    } else {
        pq_impl(blk - (NBI + 160), x0, W1a, b1a, 64, P, Q);
    }
}

__global__ void pq_kernel(const float* __restrict__ x, const float* __restrict__ W1,
                          const float* __restrict__ b1, int C_in,
                          float* __restrict__ P, float* __restrict__ Q)
{
    pq_impl(blockIdx.x, x, W1, b1, C_in, P, Q);
}

// ---------------------------------------------------------------------------
// Persistent-CTA fused EdgeConv on HMMA.
// Register-pressure build: Tlo fragments live in smem; rmax is per-chunk.
// ---------------------------------------------------------------------------
__global__ void __launch_bounds__(256, 1)
ec_hmma(const float* __restrict__ Pg, const float* __restrict__ Qg,
        const float* __restrict__ b2, const int* __restrict__ adj,
        float* __restrict__ Xout, int layer)
{
    extern __shared__ char smem[];
    const uint32_t sb = smem_to_u32(smem);
    const int tid = threadIdx.x, w = tid >> 5, lane = tid & 31;
    const int g = lane >> 2, tg = lane & 3;
    const int j0 = w * 16;
    const int rowsel = lane & 15, colsel = (lane >> 4) * 8;

    {   // stage weight tiles ONCE
        const uint4* s; uint4* d;
        s = (const uint4*)g_w1hi[layer]; d = (uint4*)(smem + OFF_W1HI);
        for (int i = tid; i < 544;  i += 256) d[i] = s[i];
        s = (const uint4*)g_w1lo[layer]; d = (uint4*)(smem + OFF_W1LO);
        for (int i = tid; i < 544;  i += 256) d[i] = s[i];
        s = (const uint4*)g_w2hi[layer]; d = (uint4*)(smem + OFF_W2HI);
        for (int i = tid; i < 2176; i += 256) d[i] = s[i];
        s = (const uint4*)g_w2lo[layer]; d = (uint4*)(smem + OFF_W2LO);
        for (int i = tid; i < 2176; i += 256) d[i] = s[i];
    }
    float* sPf  = (float*)(smem + OFF_P);
    float* sB2f = (float*)(smem + OFF_B2);
    int*   sAdj = (int*)(smem + OFF_ADJ);
    float* red  = (float*)(smem + OFF_RED);
    uint4* tlo  = (uint4*)(smem + OFF_TLO);   // [w*8+ks][lane]
    if (tid < H_) sB2f[tid] = b2[tid];

    int cur = 0;
    {
        const char* sh = (const char*)g_Ehi[blockIdx.x];
        const char* sl = (const char*)g_Elo[blockIdx.x];
        for (int i = tid; i < EBYTES/16; i += 256) {
            cp16(sb + OFF_E0 + i*16,          sh + i*16);
            cp16(sb + OFF_E0 + EBYTES + i*16, sl + i*16);
        }
        CP_COMMIT();
    }

    for (int bi = blockIdx.x; bi < NBI; bi += gridDim.x) {
        const int b = bi >> 8;
        const int nbi = bi + gridDim.x;
        float pv = (tid < H_) ? Pg[(size_t)bi*H_ + tid] : 0.f;
        int   av = adj[(size_t)bi*V_ + tid];
        if (nbi < NBI) {
            const int nb = 1 - cur;
            const char* sh = (const char*)g_Ehi[nbi];
            const char* sl = (const char*)g_Elo[nbi];
            for (int i = tid; i < EBYTES/16; i += 256) {
                cp16(sb + OFF_E0 + nb*EBUF_SZ + i*16,          sh + i*16);
                cp16(sb + OFF_E0 + nb*EBUF_SZ + EBYTES + i*16, sl + i*16);
            }
            CP_COMMIT();
            CP_WAIT1();
        } else {
            CP_WAIT0();
        }
        if (tid < H_) sPf[tid] = pv;
        sAdj[tid] = av;
        // per-warp init of this warp's red slice (no cross-warp deps)
        #pragma unroll
        for (int i = 0; i < 4; ++i) red[w*H_ + lane*4 + i] = -1e9f;
        __syncthreads();

        const uint32_t eH = sb + OFF_E0 + cur*EBUF_SZ;
        const uint32_t eL = eH + EBYTES;

        #pragma unroll
        for (int chunk = 0; chunk < 2; ++chunk) {
            const int jbase = chunk * 128;

            float acc[16][4];
            #pragma unroll
            for (int n = 0; n < 16; ++n)
                #pragma unroll
                for (int p = 0; p < 4; ++p) acc[n][p] = 0.f;

            // ---- phase 1: E @ W1c (K=32) ----
            #pragma unroll
            for (int ks = 0; ks < 2; ++ks) {
                const int k0 = ks * 16;
                uint32_t aH[4], aL[4];
                uint32_t ao = (uint32_t)((jbase + j0 + rowsel)*ST_E2 + k0 + colsel) * 2u;
                ldsm4(aH, eH + ao);
                ldsm4(aL, eL + ao);
                const uint32_t brow = (uint32_t)((k0 + rowsel)*ST_W + colsel) * 2u;
                #pragma unroll
                for (int ntp = 0; ntp < 8; ++ntp) {
                    uint32_t bo = brow + (uint32_t)(ntp*16*2);
                    uint32_t bH[4], bL[4];
                    ldsm4t(bH, sb + OFF_W1HI + bo);
                    ldsm4t(bL, sb + OFF_W1LO + bo);
                    mma_bf16(acc[2*ntp],   aH, &bH[0]);
                    mma_bf16(acc[2*ntp+1], aH, &bH[2]);
                    mma_bf16(acc[2*ntp],   aH, &bL[0]);
                    mma_bf16(acc[2*ntp+1], aH, &bL[2]);
                    mma_bf16(acc[2*ntp],   aL, &bH[0]);
                    mma_bf16(acc[2*ntp+1], aL, &bH[2]);
                }
            }

            // ---- epilogue 1: T = relu(P+Q+D); hi -> regs, lo -> smem ----
            uint32_t aH2[8][4];
            {
                const float* qA = Qg + ((size_t)(b*V_ + jbase + j0 + g))*H_;
                const float* qB = qA + 8*H_;
                #pragma unroll
                for (int ks = 0; ks < 8; ++ks) {
                    uint32_t lw[4];
                    #pragma unroll
                    for (int h = 0; h < 2; ++h) {
                        const int nt = 2*ks + h;
                        const int c = nt*8 + tg*2;
                        float2 q0 = *(const float2*)(qA + c);
                        float2 q1 = *(const float2*)(qB + c);
                        float pc0 = sPf[c], pc1 = sPf[c+1];
                        float t0 = fmaxf(acc[nt][0] + pc0 + q0.x, 0.f);
                        float t1 = fmaxf(acc[nt][1] + pc1 + q0.y, 0.f);
                        float t2 = fmaxf(acc[nt][2] + pc0 + q1.x, 0.f);
                        float t3 = fmaxf(acc[nt][3] + pc1 + q1.y, 0.f);
                        unsigned short h0=bf16b(t0), h1=bf16b(t1), h2=bf16b(t2), h3=bf16b(t3);
                        aH2[ks][0 + 2*h] = (uint32_t)h0 | ((uint32_t)h1 << 16);
                        aH2[ks][1 + 2*h] = (uint32_t)h2 | ((uint32_t)h3 << 16);
                        lw[0 + 2*h] =
                            (uint32_t)bf16b(t0-bf16f(h0)) | ((uint32_t)bf16b(t1-bf16f(h1)) << 16);
                        lw[1 + 2*h] =
                            (uint32_t)bf16b(t2-bf16f(h2)) | ((uint32_t)bf16b(t3-bf16f(h3)) << 16);
                    }
                    tlo[(w*8 + ks)*32 + lane] = make_uint4(lw[0], lw[1], lw[2], lw[3]);
                }
            }

            #pragma unroll
            for (int n = 0; n < 16; ++n)
                #pragma unroll
                for (int p = 0; p < 4; ++p) acc[n][p] = 0.f;

            // ---- phase 2: T @ W2 (K=128); A-hi from regs, A-lo 1 LDS/ks ----
            #pragma unroll
            for (int ks = 0; ks < 8; ++ks) {
                uint4 lo = tlo[(w*8 + ks)*32 + lane];
                uint32_t aL[4] = {lo.x, lo.y, lo.z, lo.w};
                const uint32_t brow = (uint32_t)((ks*16 + rowsel)*ST_W + colsel) * 2u;
                #pragma unroll
                for (int ntp = 0; ntp < 8; ++ntp) {
                    uint32_t bo = brow + (uint32_t)(ntp*16*2);
                    uint32_t bH[4], bL[4];
                    ldsm4t(bH, sb + OFF_W2HI + bo);
                    ldsm4t(bL, sb + OFF_W2LO + bo);
                    mma_bf16(acc[2*ntp],   aH2[ks], &bH[0]);
                    mma_bf16(acc[2*ntp+1], aH2[ks], &bH[2]);
                    mma_bf16(acc[2*ntp],   aH2[ks], &bL[0]);
                    mma_bf16(acc[2*ntp+1], aH2[ks], &bL[2]);
                    mma_bf16(acc[2*ntp],   aL, &bH[0]);
                    mma_bf16(acc[2*ntp+1], aL, &bH[2]);
                }
            }

            // ---- epilogue 2: relu(+b2), masked max; reduce into red now ----
            {
                float rmax[32];
                #pragma unroll
                for (int i = 0; i < 32; ++i) rmax[i] = -1e9f;
                const bool actA = sAdj[jbase + j0 + g] > 0;
                const bool actB = sAdj[jbase + j0 + 8 + g] > 0;
                #pragma unroll
                for (int nt = 0; nt < 16; ++nt) {
                    const int c = nt*8 + tg*2;
                    float b0 = sB2f[c], b1 = sB2f[c+1];
                    if (actA) {
                        rmax[2*nt]   = fmaxf(rmax[2*nt],   fmaxf(acc[nt][0]+b0, 0.f));
                        rmax[2*nt+1] = fmaxf(rmax[2*nt+1], fmaxf(acc[nt][1]+b1, 0.f));
                    }
                    if (actB) {
                        rmax[2*nt]   = fmaxf(rmax[2*nt],   fmaxf(acc[nt][2]+b0, 0.f));
                        rmax[2*nt+1] = fmaxf(rmax[2*nt+1], fmaxf(acc[nt][3]+b1, 0.f));
                    }
                }
                #pragma unroll
                for (int off = 4; off <= 16; off <<= 1)
                    #pragma unroll
                    for (int i = 0; i < 32; ++i)
                        rmax[i] = fmaxf(rmax[i], __shfl_xor_sync(0xffffffffu, rmax[i], off));
                if (lane < 4) {
                    #pragma unroll
                    for (int nt = 0; nt < 16; ++nt) {
                        int c0i = w*H_ + nt*8 + lane*2;
                        red[c0i]   = fmaxf(red[c0i],   rmax[2*nt]);
                        red[c0i+1] = fmaxf(red[c0i+1], rmax[2*nt+1]);
                    }
                }
            }
        }

        __syncthreads();
        if (tid < H_) {
            float v = red[tid];
            #pragma unroll
            for (int ww = 1; ww < 8; ++ww) v = fmaxf(v, red[ww*H_ + tid]);
            Xout[(size_t)bi*H_ + tid] = (v < -1e8f) ? 0.f : v;
        }
        __syncthreads();
        cur ^= 1;
    }
}

// ---------------------------------------------------------------------------
__global__ void __launch_bounds__(512)
rs_kernel(const float* __restrict__ x, const float* __restrict__ W3,
          const float* __restrict__ b3,
          float* __restrict__ R, float* __restrict__ S)
{
    __shared__ float sx[4][128];
    __shared__ float sr[2][4][256], ss[2][4][256];
    const int tid = threadIdx.x;
    const int cs = tid >> 8, m = tid & 255;
    const int base = blockIdx.x * 4;
    sx[tid >> 7][tid & 127] = x[(size_t)(base + (tid >> 7))*H_ + (tid & 127)];
    __syncthreads();

    const int c0 = cs * 64, c1 = c0 + 64;
    float r[4] = {0.f,0.f,0.f,0.f}, s[4] = {0.f,0.f,0.f,0.f};
    for (int c = c0; c < c1; ++c) {
        float wa = W3[c*H2_ + m], wb = W3[(128+c)*H2_ + m];
        #pragma unroll
        for (int rr = 0; rr < 4; ++rr) { r[rr] += sx[rr][c]*wa; s[rr] += sx[rr][c]*wb; }
    }
    #pragma unroll
    for (int rr = 0; rr < 4; ++rr) { sr[cs][rr][m] = r[rr]; ss[cs][rr][m] = s[rr]; }
    __syncthreads();
    if (cs == 0) {
        float bb = b3[m];
        #pragma unroll
        for (int rr = 0; rr < 4; ++rr) {
            R[(size_t)(base+rr)*H2_ + m] = sr[0][rr][m] + sr[1][rr][m];
            S[(size_t)(base+rr)*H2_ + m] = ss[0][rr][m] + ss[1][rr][m] + bb;
        }
    }
}

#define IL_ 16
#define MC_ 32
__global__ void __launch_bounds__(256)
pair_kernel(const float* __restrict__ R, const float* __restrict__ S,
            const float* __restrict__ outW, const float* __restrict__ outB,
            float* __restrict__ out)
{
    __shared__ float sR[V_][MC_+1];
    __shared__ float sS[IL_][MC_+1];
    __shared__ float sw[MC_];
    const int tid = threadIdx.x;
    const int b = blockIdx.y, i0 = blockIdx.x * IL_;
    float acc[IL_];
    #pragma unroll
    for (int il = 0; il < IL_; ++il) acc[il] = 0.f;

    for (int mc = 0; mc < H2_; mc += MC_) {
        __syncthreads();
        #pragma unroll 4
        for (int idx = tid; idx < V_*MC_; idx += 256) {
            int j = idx >> 5, mm = idx & (MC_-1);
            sR[j][mm] = R[((size_t)b*V_ + j)*H2_ + mc + mm];
        }
        for (int idx = tid; idx < IL_*MC_; idx += 256) {
            int il = idx >> 5, mm = idx & (MC_-1);
            sS[il][mm] = S[((size_t)b*V_ + i0 + il)*H2_ + mc + mm];
        }
        if (tid < MC_) sw[tid] = outW[mc + tid];
        __syncthreads();
        #pragma unroll
        for (int il = 0; il < IL_; ++il) {
            float a = 0.f;
            #pragma unroll
            for (int mm = 0; mm < MC_; ++mm)
                a += fmaxf(sR[tid][mm] + sS[il][mm], 0.f) * sw[mm];
            acc[il] += a;
        }
    }
    const float ob = outB[0];
    #pragma unroll
    for (int il = 0; il < IL_; ++il) {
        float z = acc[il] + ob;
        out[((size_t)b*V_ + i0 + il)*V_ + tid] = 1.f / (1.f + expf(-z));
    }
}

// ---------------------------------------------------------------------------
extern "C" void kernel_launch(void* const* d_in, const int* in_sizes, int n_in,
                              void* d_out, int out_size)
{
    const int*   adj   = (const int*)  d_in[0];
    const float* x0    = (const float*)d_in[1];
    const float* e     = (const float*)d_in[2];
    const float* ec1W1 = (const float*)d_in[3];
    const float* ec1b1 = (const float*)d_in[4];
    const float* ec1W2 = (const float*)d_in[5];
    const float* ec1b2 = (const float*)d_in[6];
    const float* ec2W1 = (const float*)d_in[7];
    const float* ec2b1 = (const float*)d_in[8];
    const float* ec2W2 = (const float*)d_in[9];
    const float* ec2b2 = (const float*)d_in[10];
    const float* h3W   = (const float*)d_in[11];
    const float* h3b   = (const float*)d_in[12];
    const float* outW  = (const float*)d_in[13];
    const float* outB  = (const float*)d_in[14];
    float* out = (float*)d_out;

    float *P, *Q, *X1, *X2, *R, *S;
    cudaGetSymbolAddress((void**)&P,  g_P);
    cudaGetSymbolAddress((void**)&Q,  g_Q);
    cudaGetSymbolAddress((void**)&X1, g_X1);
    cudaGetSymbolAddress((void**)&X2, g_X2);
    cudaGetSymbolAddress((void**)&R,  g_R);
    cudaGetSymbolAddress((void**)&S,  g_S);

    cudaFuncSetAttribute(ec_hmma, cudaFuncAttributeMaxDynamicSharedMemorySize, SMEM_EC);

    int sms = 148;
    cudaDeviceGetAttribute(&sms, cudaDevAttrMultiProcessorCount, 0);
    int grid = sms < NBI ? sms : NBI;

    prep_all<<<NBI + 160 + 256, 256>>>(e, ec1W1, ec1W2, ec2W1, ec2W2, x0, ec1b1, P, Q);

    ec_hmma<<<grid, 256, SMEM_EC>>>(P, Q, ec1b2, adj, X1, 0);

    pq_kernel<<<NBI/4, 256>>>(X1, ec2W1, ec2b1, 128, P, Q);
    ec_hmma<<<grid, 256, SMEM_EC>>>(P, Q, ec2b2, adj, X2, 1);

    rs_kernel<<<NBI/4, 512>>>(X2, h3W, h3b, R, S);
    dim3 pg(V_/IL_, B_);
    pair_kernel<<<pg, 256>>>(R, S, outW, outB, out);
}

// round 10
// speedup vs baseline: 1.4031x; 1.4031x over previous
#include <cuda_runtime.h>
#include <cuda_fp16.h>
#include <cstdint>

#define B_   4
#define V_   256
#define H_   128
#define KE_  32
#define H2_  256
#define ST_W 136
#define ST_E2 40
#define NBI  (B_*V_)
#define ETILE 10240
#define EBYTES 20480

__device__ float g_P [NBI*H_];
__device__ float g_Q [NBI*H_];
__device__ float g_X1[NBI*H_];
__device__ float g_X2[NBI*H_];
__device__ float g_R [NBI*H2_];
__device__ float g_S [NBI*H2_];
__device__ __align__(16) unsigned short g_w1hi[2][KE_*ST_W];
__device__ __align__(16) unsigned short g_w2hi[2][H_*ST_W];
__device__ __align__(16) unsigned short g_Ehi[NBI][ETILE];
__device__ __align__(16) unsigned short g_Elo[NBI][ETILE];

__device__ __forceinline__ unsigned short f16b(float f) {
    __half h = __float2half_rn(f);
    return *(unsigned short*)&h;
}
__device__ __forceinline__ float f16f(unsigned short u) {
    __half h = *(__half*)&u;
    return __half2float(h);
}
__device__ __forceinline__ uint32_t smem_to_u32(const void* p) {
    uint32_t a;
    asm("{ .reg .u64 t; cvta.to.shared.u64 t, %1; cvt.u32.u64 %0, t; }" : "=r"(a) : "l"(p));
    return a;
}
__device__ __forceinline__ void ldsm4(uint32_t* r, uint32_t a) {
    asm volatile("ldmatrix.sync.aligned.m8n8.x4.shared.b16 {%0,%1,%2,%3}, [%4];"
        : "=r"(r[0]), "=r"(r[1]), "=r"(r[2]), "=r"(r[3]) : "r"(a));
}
__device__ __forceinline__ void ldsm4t(uint32_t* r, uint32_t a) {
    asm volatile("ldmatrix.sync.aligned.m8n8.x4.trans.shared.b16 {%0,%1,%2,%3}, [%4];"
        : "=r"(r[0]), "=r"(r[1]), "=r"(r[2]), "=r"(r[3]) : "r"(a));
}
__device__ __forceinline__ void mma_f16(float* c, const uint32_t* a, const uint32_t* b) {
    asm volatile("mma.sync.aligned.m16n8k16.row.col.f32.f16.f16.f32 "
        "{%0,%1,%2,%3}, {%4,%5,%6,%7}, {%8,%9}, {%0,%1,%2,%3};"
        : "+f"(c[0]), "+f"(c[1]), "+f"(c[2]), "+f"(c[3])
        : "r"(a[0]), "r"(a[1]), "r"(a[2]), "r"(a[3]), "r"(b[0]), "r"(b[1]));
}
__device__ __forceinline__ void cp16(uint32_t dst, const void* src) {
    asm volatile("cp.async.cg.shared.global [%0], [%1], 16;" :: "r"(dst), "l"(src));
}
#define CP_COMMIT() asm volatile("cp.async.commit_group;" ::: "memory")
#define CP_WAIT1()  asm volatile("cp.async.wait_group 1;" ::: "memory")
#define CP_WAIT0()  asm volatile("cp.async.wait_group 0;" ::: "memory")

// SMEM byte offsets (ec kernel) — only HI weight tiles now
#define OFF_B2    0
#define OFF_P     512
#define OFF_ADJ   1024
#define OFF_RED   2048
#define OFF_W1HI  6144
#define OFF_W2HI  14848
#define OFF_E0    49664
#define EBUF_SZ   (2*EBYTES)
#define SMEM_EC   (OFF_E0 + 2*EBUF_SZ)   // 131584

// ---------------------------------------------------------------------------
__device__ __forceinline__ void pq_impl(int group, const float* __restrict__ x,
                                        const float* __restrict__ W1,
                                        const float* __restrict__ b1, int C_in,
                                        float* __restrict__ P, float* __restrict__ Q)
{
    __shared__ float sx[4][128];
    __shared__ float sp[2][4][128], sq[2][4][128];
    const int tid = threadIdx.x;
    const int cs = tid >> 7, h = tid & 127;
    const int base = group * 4;
    const int lg = (C_in == 64) ? 6 : 7;
    for (int i = tid; i < 4*C_in; i += 256)
        sx[i >> lg][i & (C_in-1)] = x[(size_t)(base + (i >> lg))*C_in + (i & (C_in-1))];
    __syncthreads();

    const int c0 = cs * (C_in >> 1), c1 = c0 + (C_in >> 1);
    float p[4] = {0.f,0.f,0.f,0.f}, q[4] = {0.f,0.f,0.f,0.f};
    for (int c = c0; c < c1; ++c) {
        float wa = W1[c*H_ + h], wb = W1[(C_in+c)*H_ + h], wd = wa - wb;
        #pragma unroll
        for (int r = 0; r < 4; ++r) { p[r] += sx[r][c]*wd; q[r] += sx[r][c]*wb; }
    }
    #pragma unroll
    for (int r = 0; r < 4; ++r) { sp[cs][r][h] = p[r]; sq[cs][r][h] = q[r]; }
    __syncthreads();
    if (cs == 0) {
        float bb = b1[h];
        #pragma unroll
        for (int r = 0; r < 4; ++r) {
            P[(size_t)(base+r)*H_ + h] = sp[0][r][h] + sp[1][r][h] + bb;
            Q[(size_t)(base+r)*H_ + h] = sq[0][r][h] + sq[1][r][h];
        }
    }
}

// Merged prep: E-convert (fp16 hi/lo) + weight prep (fp16 hi, both layers) +
// pq layer 1.  All independent block ranges.
__global__ void prep_all(const float* __restrict__ E,
                         const float* __restrict__ W1a, const float* __restrict__ W2a,
                         const float* __restrict__ W1b, const float* __restrict__ W2b,
                         const float* __restrict__ x0,  const float* __restrict__ b1a,
                         float* __restrict__ P, float* __restrict__ Q)
{
    const int blk = blockIdx.x, tid = threadIdx.x;
    if (blk < NBI) {
        unsigned short* eh = g_Ehi[blk];
        unsigned short* el = g_Elo[blk];
        for (int idx = tid; idx < 2048; idx += 256) {
            int j = idx >> 3, kq = idx & 7;
            float4 e4 = *(const float4*)(E + ((size_t)blk*V_ + j)*KE_ + kq*4);
            unsigned short h0=f16b(e4.x), h1=f16b(e4.y), h2=f16b(e4.z), h3=f16b(e4.w);
            uint2 hp, lp;
            hp.x = (uint32_t)h0 | ((uint32_t)h1 << 16);
            hp.y = (uint32_t)h2 | ((uint32_t)h3 << 16);
            lp.x = (uint32_t)f16b(e4.x-f16f(h0)) | ((uint32_t)f16b(e4.y-f16f(h1)) << 16);
            lp.y = (uint32_t)f16b(e4.z-f16f(h2)) | ((uint32_t)f16b(e4.w-f16f(h3)) << 16);
            int o = j*ST_E2 + kq*4;
            *(uint2*)(eh + o) = hp;
            *(uint2*)(el + o) = lp;
        }
    } else if (blk < NBI + 160) {
        int idx = (blk - NBI) * 256 + tid;
        if (idx < 40960) {
            int layer = idx / 20480;
            int t = idx - layer * 20480;
            const float* W1 = layer ? W1b : W1a;
            const float* W2 = layer ? W2b : W2a;
            const int C = layer ? 128 : 64;
            if (t < KE_*H_) {
                int k = t >> 7, c = t & 127;
                g_w1hi[layer][k*ST_W + c] = f16b(W1[(size_t)(2*C + k)*H_ + c]);
            } else {
                int t2 = t - KE_*H_;
                int k = t2 >> 7, c = t2 & 127;
                g_w2hi[layer][k*ST_W + c] = f16b(W2[(size_t)k*H_ + c]);
            }
        }
    } else {
        pq_impl(blk - (NBI + 160), x0, W1a, b1a, 64, P, Q);
    }
}

__global__ void pq_kernel(const float* __restrict__ x, const float* __restrict__ W1,
                          const float* __restrict__ b1, int C_in,
                          float* __restrict__ P, float* __restrict__ Q)
{
    pq_impl(blockIdx.x, x, W1, b1, C_in, P, Q);
}

// ---------------------------------------------------------------------------
// Persistent-CTA fused EdgeConv on fp16 HMMA.
// Exact A-side split (aH+aL), single-fp16 B: 4 MMAs + 1 B-ldsm per n-pair.
// ---------------------------------------------------------------------------
__global__ void __launch_bounds__(256, 1)
ec_hmma(const float* __restrict__ Pg, const float* __restrict__ Qg,
        const float* __restrict__ b2, const int* __restrict__ adj,
        float* __restrict__ Xout, int layer)
{
    extern __shared__ char smem[];
    const uint32_t sb = smem_to_u32(smem);
    const int tid = threadIdx.x, w = tid >> 5, lane = tid & 31;
    const int g = lane >> 2, tg = lane & 3;
    const int j0 = w * 16;
    const int rowsel = lane & 15, colsel = (lane >> 4) * 8;

    {   // stage weight tiles ONCE
        const uint4* s; uint4* d;
        s = (const uint4*)g_w1hi[layer]; d = (uint4*)(smem + OFF_W1HI);
        for (int i = tid; i < 544;  i += 256) d[i] = s[i];
        s = (const uint4*)g_w2hi[layer]; d = (uint4*)(smem + OFF_W2HI);
        for (int i = tid; i < 2176; i += 256) d[i] = s[i];
    }
    float* sPf  = (float*)(smem + OFF_P);
    float* sB2f = (float*)(smem + OFF_B2);
    int*   sAdj = (int*)(smem + OFF_ADJ);
    float* red  = (float*)(smem + OFF_RED);
    if (tid < H_) sB2f[tid] = b2[tid];

    int cur = 0;
    {
        const char* sh = (const char*)g_Ehi[blockIdx.x];
        const char* sl = (const char*)g_Elo[blockIdx.x];
        for (int i = tid; i < EBYTES/16; i += 256) {
            cp16(sb + OFF_E0 + i*16,          sh + i*16);
            cp16(sb + OFF_E0 + EBYTES + i*16, sl + i*16);
        }
        CP_COMMIT();
    }

    for (int bi = blockIdx.x; bi < NBI; bi += gridDim.x) {
        const int b = bi >> 8;
        const int nbi = bi + gridDim.x;
        float pv = (tid < H_) ? Pg[(size_t)bi*H_ + tid] : 0.f;
        int   av = adj[(size_t)bi*V_ + tid];
        if (nbi < NBI) {
            const int nb = 1 - cur;
            const char* sh = (const char*)g_Ehi[nbi];
            const char* sl = (const char*)g_Elo[nbi];
            for (int i = tid; i < EBYTES/16; i += 256) {
                cp16(sb + OFF_E0 + nb*EBUF_SZ + i*16,          sh + i*16);
                cp16(sb + OFF_E0 + nb*EBUF_SZ + EBYTES + i*16, sl + i*16);
            }
            CP_COMMIT();
            CP_WAIT1();
        } else {
            CP_WAIT0();
        }
        if (tid < H_) sPf[tid] = pv;
        sAdj[tid] = av;
        __syncthreads();

        const uint32_t eH = sb + OFF_E0 + cur*EBUF_SZ;
        const uint32_t eL = eH + EBYTES;

        float rmax[32];
        #pragma unroll
        for (int i = 0; i < 32; ++i) rmax[i] = -1e9f;

        #pragma unroll
        for (int chunk = 0; chunk < 2; ++chunk) {
            const int jbase = chunk * 128;

            float acc[16][4];
            #pragma unroll
            for (int n = 0; n < 16; ++n)
                #pragma unroll
                for (int p = 0; p < 4; ++p) acc[n][p] = 0.f;

            // ---- phase 1: E @ W1c (K=32), A split exact, B single fp16 ----
            #pragma unroll
            for (int ks = 0; ks < 2; ++ks) {
                const int k0 = ks * 16;
                uint32_t aH[4], aL[4];
                uint32_t ao = (uint32_t)((jbase + j0 + rowsel)*ST_E2 + k0 + colsel) * 2u;
                ldsm4(aH, eH + ao);
                ldsm4(aL, eL + ao);
                const uint32_t brow = (uint32_t)((k0 + rowsel)*ST_W + colsel) * 2u;
                #pragma unroll
                for (int ntp = 0; ntp < 8; ++ntp) {
                    uint32_t bH[4];
                    ldsm4t(bH, sb + OFF_W1HI + brow + (uint32_t)(ntp*16*2));
                    mma_f16(acc[2*ntp],   aH, &bH[0]);
                    mma_f16(acc[2*ntp+1], aH, &bH[2]);
                    mma_f16(acc[2*ntp],   aL, &bH[0]);
                    mma_f16(acc[2*ntp+1], aL, &bH[2]);
                }
            }

            // ---- epilogue 1: T = relu(P + Q + D) -> A-fragments in registers ----
            uint32_t aH2[8][4], aL2[8][4];
            {
                const float* qA = Qg + ((size_t)(b*V_ + jbase + j0 + g))*H_;
                const float* qB = qA + 8*H_;
                #pragma unroll
                for (int ks = 0; ks < 8; ++ks) {
                    #pragma unroll
                    for (int h = 0; h < 2; ++h) {
                        const int nt = 2*ks + h;
                        const int c = nt*8 + tg*2;
                        float2 q0 = *(const float2*)(qA + c);
                        float2 q1 = *(const float2*)(qB + c);
                        float pc0 = sPf[c], pc1 = sPf[c+1];
                        float t0 = fmaxf(acc[nt][0] + pc0 + q0.x, 0.f);
                        float t1 = fmaxf(acc[nt][1] + pc1 + q0.y, 0.f);
                        float t2 = fmaxf(acc[nt][2] + pc0 + q1.x, 0.f);
                        float t3 = fmaxf(acc[nt][3] + pc1 + q1.y, 0.f);
                        unsigned short h0=f16b(t0), h1=f16b(t1), h2=f16b(t2), h3=f16b(t3);
                        aH2[ks][0 + 2*h] = (uint32_t)h0 | ((uint32_t)h1 << 16);
                        aH2[ks][1 + 2*h] = (uint32_t)h2 | ((uint32_t)h3 << 16);
                        aL2[ks][0 + 2*h] =
                            (uint32_t)f16b(t0-f16f(h0)) | ((uint32_t)f16b(t1-f16f(h1)) << 16);
                        aL2[ks][1 + 2*h] =
                            (uint32_t)f16b(t2-f16f(h2)) | ((uint32_t)f16b(t3-f16f(h3)) << 16);
                    }
                }
            }

            #pragma unroll
            for (int n = 0; n < 16; ++n)
                #pragma unroll
                for (int p = 0; p < 4; ++p) acc[n][p] = 0.f;

            // ---- phase 2: T @ W2 (K=128), A from registers, B single fp16 ----
            #pragma unroll
            for (int ks = 0; ks < 8; ++ks) {
                const uint32_t brow = (uint32_t)((ks*16 + rowsel)*ST_W + colsel) * 2u;
                #pragma unroll
                for (int ntp = 0; ntp < 8; ++ntp) {
                    uint32_t bH[4];
                    ldsm4t(bH, sb + OFF_W2HI + brow + (uint32_t)(ntp*16*2));
                    mma_f16(acc[2*ntp],   aH2[ks], &bH[0]);
                    mma_f16(acc[2*ntp+1], aH2[ks], &bH[2]);
                    mma_f16(acc[2*ntp],   aL2[ks], &bH[0]);
                    mma_f16(acc[2*ntp+1], aL2[ks], &bH[2]);
                }
            }

            // ---- epilogue 2: relu(+b2), adjacency-masked col-max ----
            {
                const bool actA = sAdj[jbase + j0 + g] > 0;
                const bool actB = sAdj[jbase + j0 + 8 + g] > 0;
                #pragma unroll
                for (int nt = 0; nt < 16; ++nt) {
                    const int c = nt*8 + tg*2;
                    float b0 = sB2f[c], b1 = sB2f[c+1];
                    if (actA) {
                        rmax[2*nt]   = fmaxf(rmax[2*nt],   fmaxf(acc[nt][0]+b0, 0.f));
                        rmax[2*nt+1] = fmaxf(rmax[2*nt+1], fmaxf(acc[nt][1]+b1, 0.f));
                    }
                    if (actB) {
                        rmax[2*nt]   = fmaxf(rmax[2*nt],   fmaxf(acc[nt][2]+b0, 0.f));
                        rmax[2*nt+1] = fmaxf(rmax[2*nt+1], fmaxf(acc[nt][3]+b1, 0.f));
                    }
                }
            }
        }

        // reduce over g, then over warps via smem
        #pragma unroll
        for (int off = 4; off <= 16; off <<= 1)
            #pragma unroll
            for (int i = 0; i < 32; ++i)
                rmax[i] = fmaxf(rmax[i], __shfl_xor_sync(0xffffffffu, rmax[i], off));

        if (lane < 4) {
            #pragma unroll
            for (int nt = 0; nt < 16; ++nt) {
                red[w*H_ + nt*8 + lane*2]     = rmax[2*nt];
                red[w*H_ + nt*8 + lane*2 + 1] = rmax[2*nt+1];
            }
        }
        __syncthreads();
        if (tid < H_) {
            float v = red[tid];
            #pragma unroll
            for (int ww = 1; ww < 8; ++ww) v = fmaxf(v, red[ww*H_ + tid]);
            Xout[(size_t)bi*H_ + tid] = (v < -1e8f) ? 0.f : v;
        }
        __syncthreads();
        cur ^= 1;
    }
}

// ---------------------------------------------------------------------------
__global__ void __launch_bounds__(512)
rs_kernel(const float* __restrict__ x, const float* __restrict__ W3,
          const float* __restrict__ b3,
          float* __restrict__ R, float* __restrict__ S)
{
    __shared__ float sx[4][128];
    __shared__ float sr[2][4][256], ss[2][4][256];
    const int tid = threadIdx.x;
    const int cs = tid >> 8, m = tid & 255;
    const int base = blockIdx.x * 4;
    sx[tid >> 7][tid & 127] = x[(size_t)(base + (tid >> 7))*H_ + (tid & 127)];
    __syncthreads();

    const int c0 = cs * 64, c1 = c0 + 64;
    float r[4] = {0.f,0.f,0.f,0.f}, s[4] = {0.f,0.f,0.f,0.f};
    for (int c = c0; c < c1; ++c) {
        float wa = W3[c*H2_ + m], wb = W3[(128+c)*H2_ + m];
        #pragma unroll
        for (int rr = 0; rr < 4; ++rr) { r[rr] += sx[rr][c]*wa; s[rr] += sx[rr][c]*wb; }
    }
    #pragma unroll
    for (int rr = 0; rr < 4; ++rr) { sr[cs][rr][m] = r[rr]; ss[cs][rr][m] = s[rr]; }
    __syncthreads();
    if (cs == 0) {
        float bb = b3[m];
        #pragma unroll
        for (int rr = 0; rr < 4; ++rr) {
            R[(size_t)(base+rr)*H2_ + m] = sr[0][rr][m] + sr[1][rr][m];
            S[(size_t)(base+rr)*H2_ + m] = ss[0][rr][m] + ss[1][rr][m] + bb;
        }
    }
}

#define IL_ 8
#define MC_ 32
__global__ void __launch_bounds__(256)
pair_kernel(const float* __restrict__ R, const float* __restrict__ S,
            const float* __restrict__ outW, const float* __restrict__ outB,
            float* __restrict__ out)
{
    __shared__ float sR[V_][MC_+1];
    __shared__ float sS[IL_][MC_+1];
    __shared__ float sw[MC_];
    const int tid = threadIdx.x;
    const int b = blockIdx.y, i0 = blockIdx.x * IL_;
    float acc[IL_];
    #pragma unroll
    for (int il = 0; il < IL_; ++il) acc[il] = 0.f;

    for (int mc = 0; mc < H2_; mc += MC_) {
        __syncthreads();
        #pragma unroll 4
        for (int idx = tid; idx < V_*MC_; idx += 256) {
            int j = idx >> 5, mm = idx & (MC_-1);
            sR[j][mm] = R[((size_t)b*V_ + j)*H2_ + mc + mm];
        }
        if (tid < IL_*MC_) {
            int il = tid >> 5, mm = tid & (MC_-1);
            sS[il][mm] = S[((size_t)b*V_ + i0 + il)*H2_ + mc + mm];
        }
        if (tid < MC_) sw[tid] = outW[mc + tid];
        __syncthreads();
        #pragma unroll
        for (int il = 0; il < IL_; ++il) {
            float a = 0.f;
            #pragma unroll
            for (int mm = 0; mm < MC_; ++mm)
                a += fmaxf(sR[tid][mm] + sS[il][mm], 0.f) * sw[mm];
            acc[il] += a;
        }
    }
    const float ob = outB[0];
    #pragma unroll
    for (int il = 0; il < IL_; ++il) {
        float z = acc[il] + ob;
        out[((size_t)b*V_ + i0 + il)*V_ + tid] = 1.f / (1.f + expf(-z));
    }
}

// ---------------------------------------------------------------------------
extern "C" void kernel_launch(void* const* d_in, const int* in_sizes, int n_in,
                              void* d_out, int out_size)
{
    const int*   adj   = (const int*)  d_in[0];
    const float* x0    = (const float*)d_in[1];
    const float* e     = (const float*)d_in[2];
    const float* ec1W1 = (const float*)d_in[3];
    const float* ec1b1 = (const float*)d_in[4];
    const float* ec1W2 = (const float*)d_in[5];
    const float* ec1b2 = (const float*)d_in[6];
    const float* ec2W1 = (const float*)d_in[7];
    const float* ec2b1 = (const float*)d_in[8];
    const float* ec2W2 = (const float*)d_in[9];
    const float* ec2b2 = (const float*)d_in[10];
    const float* h3W   = (const float*)d_in[11];
    const float* h3b   = (const float*)d_in[12];
    const float* outW  = (const float*)d_in[13];
    const float* outB  = (const float*)d_in[14];
    float* out = (float*)d_out;

    float *P, *Q, *X1, *X2, *R, *S;
    cudaGetSymbolAddress((void**)&P,  g_P);
    cudaGetSymbolAddress((void**)&Q,  g_Q);
    cudaGetSymbolAddress((void**)&X1, g_X1);
    cudaGetSymbolAddress((void**)&X2, g_X2);
    cudaGetSymbolAddress((void**)&R,  g_R);
    cudaGetSymbolAddress((void**)&S,  g_S);

    cudaFuncSetAttribute(ec_hmma, cudaFuncAttributeMaxDynamicSharedMemorySize, SMEM_EC);

    int sms = 148;
    cudaDeviceGetAttribute(&sms, cudaDevAttrMultiProcessorCount, 0);
    int grid = sms < NBI ? sms : NBI;

    prep_all<<<NBI + 160 + 256, 256>>>(e, ec1W1, ec1W2, ec2W1, ec2W2, x0, ec1b1, P, Q);

    ec_hmma<<<grid, 256, SMEM_EC>>>(P, Q, ec1b2, adj, X1, 0);

    pq_kernel<<<NBI/4, 256>>>(X1, ec2W1, ec2b1, 128, P, Q);
    ec_hmma<<<grid, 256, SMEM_EC>>>(P, Q, ec2b2, adj, X2, 1);

    rs_kernel<<<NBI/4, 512>>>(X2, h3W, h3b, R, S);
    dim3 pg(V_/IL_, B_);
    pair_kernel<<<pg, 256>>>(R, S, outW, outB, out);
}

// round 11
// speedup vs baseline: 1.6529x; 1.1781x over previous
#include <cuda_runtime.h>
#include <cuda_fp16.h>
#include <cstdint>

#define B_   4
#define V_   256
#define H_   128
#define KE_  32
#define H2_  256
#define ST_W 136
#define ST_E2 40
#define NBI  (B_*V_)
#define ETILE 10240
#define EBYTES 20480

__device__ float g_P [NBI*H_];
__device__ float g_Q [NBI*H_];
__device__ float g_X1[NBI*H_];
__device__ float g_X2[NBI*H_];
__device__ float g_R [NBI*H2_];
__device__ float g_S [NBI*H2_];
__device__ __align__(16) unsigned short g_w1hi[2][KE_*ST_W];
__device__ __align__(16) unsigned short g_w2hi[2][H_*ST_W];
__device__ __align__(16) unsigned short g_Ehi[NBI][ETILE];

__device__ __forceinline__ unsigned short f16b(float f) {
    __half h = __float2half_rn(f);
    return *(unsigned short*)&h;
}
__device__ __forceinline__ uint32_t smem_to_u32(const void* p) {
    uint32_t a;
    asm("{ .reg .u64 t; cvta.to.shared.u64 t, %1; cvt.u32.u64 %0, t; }" : "=r"(a) : "l"(p));
    return a;
}
__device__ __forceinline__ void ldsm4(uint32_t* r, uint32_t a) {
    asm volatile("ldmatrix.sync.aligned.m8n8.x4.shared.b16 {%0,%1,%2,%3}, [%4];"
        : "=r"(r[0]), "=r"(r[1]), "=r"(r[2]), "=r"(r[3]) : "r"(a));
}
__device__ __forceinline__ void ldsm4t(uint32_t* r, uint32_t a) {
    asm volatile("ldmatrix.sync.aligned.m8n8.x4.trans.shared.b16 {%0,%1,%2,%3}, [%4];"
        : "=r"(r[0]), "=r"(r[1]), "=r"(r[2]), "=r"(r[3]) : "r"(a));
}
__device__ __forceinline__ void mma_f16(float* c, const uint32_t* a, const uint32_t* b) {
    asm volatile("mma.sync.aligned.m16n8k16.row.col.f32.f16.f16.f32 "
        "{%0,%1,%2,%3}, {%4,%5,%6,%7}, {%8,%9}, {%0,%1,%2,%3};"
        : "+f"(c[0]), "+f"(c[1]), "+f"(c[2]), "+f"(c[3])
        : "r"(a[0]), "r"(a[1]), "r"(a[2]), "r"(a[3]), "r"(b[0]), "r"(b[1]));
}
__device__ __forceinline__ void cp16(uint32_t dst, const void* src) {
    asm volatile("cp.async.cg.shared.global [%0], [%1], 16;" :: "r"(dst), "l"(src));
}
#define CP_COMMIT() asm volatile("cp.async.commit_group;" ::: "memory")
#define CP_WAIT1()  asm volatile("cp.async.wait_group 1;" ::: "memory")
#define CP_WAIT0()  asm volatile("cp.async.wait_group 0;" ::: "memory")

// SMEM byte offsets (ec kernel) — single-fp16 E, hi-only weights
#define OFF_B2    0
#define OFF_P     512
#define OFF_ADJ   1024
#define OFF_RED   2048
#define OFF_W1HI  6144
#define OFF_W2HI  14848
#define OFF_E0    49664
#define SMEM_EC   (OFF_E0 + 2*EBYTES)   // 90624

// ---------------------------------------------------------------------------
__device__ __forceinline__ void pq_impl(int group, const float* __restrict__ x,
                                        const float* __restrict__ W1,
                                        const float* __restrict__ b1, int C_in,
                                        float* __restrict__ P, float* __restrict__ Q)
{
    __shared__ float sx[4][128];
    __shared__ float sp[2][4][128], sq[2][4][128];
    const int tid = threadIdx.x;
    const int cs = tid >> 7, h = tid & 127;
    const int base = group * 4;
    const int lg = (C_in == 64) ? 6 : 7;
    for (int i = tid; i < 4*C_in; i += 256)
        sx[i >> lg][i & (C_in-1)] = x[(size_t)(base + (i >> lg))*C_in + (i & (C_in-1))];
    __syncthreads();

    const int c0 = cs * (C_in >> 1), c1 = c0 + (C_in >> 1);
    float p[4] = {0.f,0.f,0.f,0.f}, q[4] = {0.f,0.f,0.f,0.f};
    for (int c = c0; c < c1; ++c) {
        float wa = W1[c*H_ + h], wb = W1[(C_in+c)*H_ + h], wd = wa - wb;
        #pragma unroll
        for (int r = 0; r < 4; ++r) { p[r] += sx[r][c]*wd; q[r] += sx[r][c]*wb; }
    }
    #pragma unroll
    for (int r = 0; r < 4; ++r) { sp[cs][r][h] = p[r]; sq[cs][r][h] = q[r]; }
    __syncthreads();
    if (cs == 0) {
        float bb = b1[h];
        #pragma unroll
        for (int r = 0; r < 4; ++r) {
            P[(size_t)(base+r)*H_ + h] = sp[0][r][h] + sp[1][r][h] + bb;
            Q[(size_t)(base+r)*H_ + h] = sq[0][r][h] + sq[1][r][h];
        }
    }
}

// Merged prep: E-convert (single fp16) + weight prep (fp16, both layers) +
// pq layer 1.  All independent block ranges.
__global__ void prep_all(const float* __restrict__ E,
                         const float* __restrict__ W1a, const float* __restrict__ W2a,
                         const float* __restrict__ W1b, const float* __restrict__ W2b,
                         const float* __restrict__ x0,  const float* __restrict__ b1a,
                         float* __restrict__ P, float* __restrict__ Q)
{
    const int blk = blockIdx.x, tid = threadIdx.x;
    if (blk < NBI) {
        unsigned short* eh = g_Ehi[blk];
        for (int idx = tid; idx < 2048; idx += 256) {
            int j = idx >> 3, kq = idx & 7;
            float4 e4 = *(const float4*)(E + ((size_t)blk*V_ + j)*KE_ + kq*4);
            uint2 hp;
            hp.x = (uint32_t)f16b(e4.x) | ((uint32_t)f16b(e4.y) << 16);
            hp.y = (uint32_t)f16b(e4.z) | ((uint32_t)f16b(e4.w) << 16);
            *(uint2*)(eh + j*ST_E2 + kq*4) = hp;
        }
    } else if (blk < NBI + 160) {
        int idx = (blk - NBI) * 256 + tid;
        if (idx < 40960) {
            int layer = idx / 20480;
            int t = idx - layer * 20480;
            const float* W1 = layer ? W1b : W1a;
            const float* W2 = layer ? W2b : W2a;
            const int C = layer ? 128 : 64;
            if (t < KE_*H_) {
                int k = t >> 7, c = t & 127;
                g_w1hi[layer][k*ST_W + c] = f16b(W1[(size_t)(2*C + k)*H_ + c]);
            } else {
                int t2 = t - KE_*H_;
                int k = t2 >> 7, c = t2 & 127;
                g_w2hi[layer][k*ST_W + c] = f16b(W2[(size_t)k*H_ + c]);
            }
        }
    } else {
        pq_impl(blk - (NBI + 160), x0, W1a, b1a, 64, P, Q);
    }
}

__global__ void pq_kernel(const float* __restrict__ x, const float* __restrict__ W1,
                          const float* __restrict__ b1, int C_in,
                          float* __restrict__ P, float* __restrict__ Q)
{
    pq_impl(blockIdx.x, x, W1, b1, C_in, P, Q);
}

// ---------------------------------------------------------------------------
// Persistent-CTA fused EdgeConv, full single-fp16 HMMA.
// ---------------------------------------------------------------------------
__global__ void __launch_bounds__(256, 1)
ec_hmma(const float* __restrict__ Pg, const float* __restrict__ Qg,
        const float* __restrict__ b2, const int* __restrict__ adj,
        float* __restrict__ Xout, int layer)
{
    extern __shared__ char smem[];
    const uint32_t sb = smem_to_u32(smem);
    const int tid = threadIdx.x, w = tid >> 5, lane = tid & 31;
    const int g = lane >> 2, tg = lane & 3;
    const int j0 = w * 16;
    const int rowsel = lane & 15, colsel = (lane >> 4) * 8;

    {   // stage weight tiles ONCE
        const uint4* s; uint4* d;
        s = (const uint4*)g_w1hi[layer]; d = (uint4*)(smem + OFF_W1HI);
        for (int i = tid; i < 544;  i += 256) d[i] = s[i];
        s = (const uint4*)g_w2hi[layer]; d = (uint4*)(smem + OFF_W2HI);
        for (int i = tid; i < 2176; i += 256) d[i] = s[i];
    }
    float* sPf  = (float*)(smem + OFF_P);
    float* sB2f = (float*)(smem + OFF_B2);
    int*   sAdj = (int*)(smem + OFF_ADJ);
    float* red  = (float*)(smem + OFF_RED);
    if (tid < H_) sB2f[tid] = b2[tid];

    int cur = 0;
    {
        const char* sh = (const char*)g_Ehi[blockIdx.x];
        for (int i = tid; i < EBYTES/16; i += 256)
            cp16(sb + OFF_E0 + i*16, sh + i*16);
        CP_COMMIT();
    }

    for (int bi = blockIdx.x; bi < NBI; bi += gridDim.x) {
        const int b = bi >> 8;
        const int nbi = bi + gridDim.x;
        float pv = (tid < H_) ? Pg[(size_t)bi*H_ + tid] : 0.f;
        int   av = adj[(size_t)bi*V_ + tid];
        if (nbi < NBI) {
            const int nb = 1 - cur;
            const char* sh = (const char*)g_Ehi[nbi];
            for (int i = tid; i < EBYTES/16; i += 256)
                cp16(sb + OFF_E0 + nb*EBYTES + i*16, sh + i*16);
            CP_COMMIT();
            CP_WAIT1();
        } else {
            CP_WAIT0();
        }
        if (tid < H_) sPf[tid] = pv;
        sAdj[tid] = av;
        __syncthreads();

        const uint32_t eH = sb + OFF_E0 + cur*EBYTES;

        float rmax[32];
        #pragma unroll
        for (int i = 0; i < 32; ++i) rmax[i] = -1e9f;

        #pragma unroll
        for (int chunk = 0; chunk < 2; ++chunk) {
            const int jbase = chunk * 128;

            float acc[16][4];
            #pragma unroll
            for (int n = 0; n < 16; ++n)
                #pragma unroll
                for (int p = 0; p < 4; ++p) acc[n][p] = 0.f;

            // ---- phase 1: E @ W1c (K=32), single fp16 ----
            #pragma unroll
            for (int ks = 0; ks < 2; ++ks) {
                const int k0 = ks * 16;
                uint32_t aH[4];
                uint32_t ao = (uint32_t)((jbase + j0 + rowsel)*ST_E2 + k0 + colsel) * 2u;
                ldsm4(aH, eH + ao);
                const uint32_t brow = (uint32_t)((k0 + rowsel)*ST_W + colsel) * 2u;
                #pragma unroll
                for (int ntp = 0; ntp < 8; ++ntp) {
                    uint32_t bH[4];
                    ldsm4t(bH, sb + OFF_W1HI + brow + (uint32_t)(ntp*16*2));
                    mma_f16(acc[2*ntp],   aH, &bH[0]);
                    mma_f16(acc[2*ntp+1], aH, &bH[2]);
                }
            }

            // ---- epilogue 1: T = relu(P + Q + D) -> fp16 A-fragments ----
            uint32_t aH2[8][4];
            {
                const float* qA = Qg + ((size_t)(b*V_ + jbase + j0 + g))*H_;
                const float* qB = qA + 8*H_;
                #pragma unroll
                for (int ks = 0; ks < 8; ++ks) {
                    #pragma unroll
                    for (int h = 0; h < 2; ++h) {
                        const int nt = 2*ks + h;
                        const int c = nt*8 + tg*2;
                        float2 q0 = *(const float2*)(qA + c);
                        float2 q1 = *(const float2*)(qB + c);
                        float pc0 = sPf[c], pc1 = sPf[c+1];
                        float t0 = fmaxf(acc[nt][0] + pc0 + q0.x, 0.f);
                        float t1 = fmaxf(acc[nt][1] + pc1 + q0.y, 0.f);
                        float t2 = fmaxf(acc[nt][2] + pc0 + q1.x, 0.f);
                        float t3 = fmaxf(acc[nt][3] + pc1 + q1.y, 0.f);
                        aH2[ks][0 + 2*h] = (uint32_t)f16b(t0) | ((uint32_t)f16b(t1) << 16);
                        aH2[ks][1 + 2*h] = (uint32_t)f16b(t2) | ((uint32_t)f16b(t3) << 16);
                    }
                }
            }

            #pragma unroll
            for (int n = 0; n < 16; ++n)
                #pragma unroll
                for (int p = 0; p < 4; ++p) acc[n][p] = 0.f;

            // ---- phase 2: T @ W2 (K=128), A from registers, single fp16 ----
            #pragma unroll
            for (int ks = 0; ks < 8; ++ks) {
                const uint32_t brow = (uint32_t)((ks*16 + rowsel)*ST_W + colsel) * 2u;
                #pragma unroll
                for (int ntp = 0; ntp < 8; ++ntp) {
                    uint32_t bH[4];
                    ldsm4t(bH, sb + OFF_W2HI + brow + (uint32_t)(ntp*16*2));
                    mma_f16(acc[2*ntp],   aH2[ks], &bH[0]);
                    mma_f16(acc[2*ntp+1], aH2[ks], &bH[2]);
                }
            }

            // ---- epilogue 2: relu(+b2), adjacency-masked col-max ----
            {
                const bool actA = sAdj[jbase + j0 + g] > 0;
                const bool actB = sAdj[jbase + j0 + 8 + g] > 0;
                #pragma unroll
                for (int nt = 0; nt < 16; ++nt) {
                    const int c = nt*8 + tg*2;
                    float b0 = sB2f[c], b1 = sB2f[c+1];
                    if (actA) {
                        rmax[2*nt]   = fmaxf(rmax[2*nt],   fmaxf(acc[nt][0]+b0, 0.f));
                        rmax[2*nt+1] = fmaxf(rmax[2*nt+1], fmaxf(acc[nt][1]+b1, 0.f));
                    }
                    if (actB) {
                        rmax[2*nt]   = fmaxf(rmax[2*nt],   fmaxf(acc[nt][2]+b0, 0.f));
                        rmax[2*nt+1] = fmaxf(rmax[2*nt+1], fmaxf(acc[nt][3]+b1, 0.f));
                    }
                }
            }
        }

        // reduce over g, then over warps via smem
        #pragma unroll
        for (int off = 4; off <= 16; off <<= 1)
            #pragma unroll
            for (int i = 0; i < 32; ++i)
                rmax[i] = fmaxf(rmax[i], __shfl_xor_sync(0xffffffffu, rmax[i], off));

        if (lane < 4) {
            #pragma unroll
            for (int nt = 0; nt < 16; ++nt) {
                red[w*H_ + nt*8 + lane*2]     = rmax[2*nt];
                red[w*H_ + nt*8 + lane*2 + 1] = rmax[2*nt+1];
            }
        }
        __syncthreads();
        if (tid < H_) {
            float v = red[tid];
            #pragma unroll
            for (int ww = 1; ww < 8; ++ww) v = fmaxf(v, red[ww*H_ + tid]);
            Xout[(size_t)bi*H_ + tid] = (v < -1e8f) ? 0.f : v;
        }
        __syncthreads();
        cur ^= 1;
    }
}

// ---------------------------------------------------------------------------
__global__ void __launch_bounds__(512)
rs_kernel(const float* __restrict__ x, const float* __restrict__ W3,
          const float* __restrict__ b3,
          float* __restrict__ R, float* __restrict__ S)
{
    __shared__ float sx[4][128];
    __shared__ float sr[2][4][256], ss[2][4][256];
    const int tid = threadIdx.x;
    const int cs = tid >> 8, m = tid & 255;
    const int base = blockIdx.x * 4;
    sx[tid >> 7][tid & 127] = x[(size_t)(base + (tid >> 7))*H_ + (tid & 127)];
    __syncthreads();

    const int c0 = cs * 64, c1 = c0 + 64;
    float r[4] = {0.f,0.f,0.f,0.f}, s[4] = {0.f,0.f,0.f,0.f};
    for (int c = c0; c < c1; ++c) {
        float wa = W3[c*H2_ + m], wb = W3[(128+c)*H2_ + m];
        #pragma unroll
        for (int rr = 0; rr < 4; ++rr) { r[rr] += sx[rr][c]*wa; s[rr] += sx[rr][c]*wb; }
    }
    #pragma unroll
    for (int rr = 0; rr < 4; ++rr) { sr[cs][rr][m] = r[rr]; ss[cs][rr][m] = s[rr]; }
    __syncthreads();
    if (cs == 0) {
        float bb = b3[m];
        #pragma unroll
        for (int rr = 0; rr < 4; ++rr) {
            R[(size_t)(base+rr)*H2_ + m] = sr[0][rr][m] + sr[1][rr][m];
            S[(size_t)(base+rr)*H2_ + m] = ss[0][rr][m] + ss[1][rr][m] + bb;
        }
    }
}

#define IL_ 8
#define MC_ 32
__global__ void __launch_bounds__(256)
pair_kernel(const float* __restrict__ R, const float* __restrict__ S,
            const float* __restrict__ outW, const float* __restrict__ outB,
            float* __restrict__ out)
{
    __shared__ float sR[V_][MC_+1];
    __shared__ float sS[IL_][MC_+1];
    __shared__ float sw[MC_];
    const int tid = threadIdx.x;
    const int b = blockIdx.y, i0 = blockIdx.x * IL_;
    float acc[IL_];
    #pragma unroll
    for (int il = 0; il < IL_; ++il) acc[il] = 0.f;

    for (int mc = 0; mc < H2_; mc += MC_) {
        __syncthreads();
        #pragma unroll 4
        for (int idx = tid; idx < V_*MC_; idx += 256) {
            int j = idx >> 5, mm = idx & (MC_-1);
            sR[j][mm] = R[((size_t)b*V_ + j)*H2_ + mc + mm];
        }
        if (tid < IL_*MC_) {
            int il = tid >> 5, mm = tid & (MC_-1);
            sS[il][mm] = S[((size_t)b*V_ + i0 + il)*H2_ + mc + mm];
        }
        if (tid < MC_) sw[tid] = outW[mc + tid];
        __syncthreads();
        #pragma unroll
        for (int il = 0; il < IL_; ++il) {
            float a = 0.f;
            #pragma unroll
            for (int mm = 0; mm < MC_; ++mm)
                a += fmaxf(sR[tid][mm] + sS[il][mm], 0.f) * sw[mm];
            acc[il] += a;
        }
    }
    const float ob = outB[0];
    #pragma unroll
    for (int il = 0; il < IL_; ++il) {
        float z = acc[il] + ob;
        out[((size_t)b*V_ + i0 + il)*V_ + tid] = 1.f / (1.f + expf(-z));
    }
}

// ---------------------------------------------------------------------------
extern "C" void kernel_launch(void* const* d_in, const int* in_sizes, int n_in,
                              void* d_out, int out_size)
{
    const int*   adj   = (const int*)  d_in[0];
    const float* x0    = (const float*)d_in[1];
    const float* e     = (const float*)d_in[2];
    const float* ec1W1 = (const float*)d_in[3];
    const float* ec1b1 = (const float*)d_in[4];
    const float* ec1W2 = (const float*)d_in[5];
    const float* ec1b2 = (const float*)d_in[6];
    const float* ec2W1 = (const float*)d_in[7];
    const float* ec2b1 = (const float*)d_in[8];
    const float* ec2W2 = (const float*)d_in[9];
    const float* ec2b2 = (const float*)d_in[10];
    const float* h3W   = (const float*)d_in[11];
    const float* h3b   = (const float*)d_in[12];
    const float* outW  = (const float*)d_in[13];
    const float* outB  = (const float*)d_in[14];
    float* out = (float*)d_out;

    float *P, *Q, *X1, *X2, *R, *S;
    cudaGetSymbolAddress((void**)&P,  g_P);
    cudaGetSymbolAddress((void**)&Q,  g_Q);
    cudaGetSymbolAddress((void**)&X1, g_X1);
    cudaGetSymbolAddress((void**)&X2, g_X2);
    cudaGetSymbolAddress((void**)&R,  g_R);
    cudaGetSymbolAddress((void**)&S,  g_S);

    cudaFuncSetAttribute(ec_hmma, cudaFuncAttributeMaxDynamicSharedMemorySize, SMEM_EC);

    int sms = 148;
    cudaDeviceGetAttribute(&sms, cudaDevAttrMultiProcessorCount, 0);
    int grid = sms < NBI ? sms : NBI;

    prep_all<<<NBI + 160 + 256, 256>>>(e, ec1W1, ec1W2, ec2W1, ec2W2, x0, ec1b1, P, Q);

    ec_hmma<<<grid, 256, SMEM_EC>>>(P, Q, ec1b2, adj, X1, 0);

    pq_kernel<<<NBI/4, 256>>>(X1, ec2W1, ec2b1, 128, P, Q);
    ec_hmma<<<grid, 256, SMEM_EC>>>(P, Q, ec2b2, adj, X2, 1);

    rs_kernel<<<NBI/4, 512>>>(X2, h3W, h3b, R, S);
    dim3 pg(V_/IL_, B_);
    pair_kernel<<<pg, 256>>>(R, S, outW, outB, out);
}

// round 12
// speedup vs baseline: 1.7130x; 1.0363x over previous
#include <cuda_runtime.h>
#include <cuda_fp16.h>
#include <cstdint>

#define B_   4
#define V_   256
#define H_   128
#define KE_  32
#define H2_  256
#define ST_W 136
#define ST_E2 40
#define NBI  (B_*V_)
#define ETILE 10240
#define EBYTES 20480

__device__ float g_P [NBI*H_];
__device__ float g_Q [NBI*H_];
__device__ float g_X1[NBI*H_];
__device__ float g_X2[NBI*H_];
__device__ float g_R [NBI*H2_];
__device__ float g_S [NBI*H2_];
__device__ __align__(16) unsigned short g_w1hi[2][KE_*ST_W];
__device__ __align__(16) unsigned short g_w2hi[2][H_*ST_W];
__device__ __align__(16) unsigned short g_Ehi[NBI][ETILE];

__device__ __forceinline__ unsigned short f16b(float f) {
    __half h = __float2half_rn(f);
    return *(unsigned short*)&h;
}
__device__ __forceinline__ uint32_t smem_to_u32(const void* p) {
    uint32_t a;
    asm("{ .reg .u64 t; cvta.to.shared.u64 t, %1; cvt.u32.u64 %0, t; }" : "=r"(a) : "l"(p));
    return a;
}
__device__ __forceinline__ void ldsm4(uint32_t* r, uint32_t a) {
    asm volatile("ldmatrix.sync.aligned.m8n8.x4.shared.b16 {%0,%1,%2,%3}, [%4];"
        : "=r"(r[0]), "=r"(r[1]), "=r"(r[2]), "=r"(r[3]) : "r"(a));
}
__device__ __forceinline__ void ldsm4t(uint32_t* r, uint32_t a) {
    asm volatile("ldmatrix.sync.aligned.m8n8.x4.trans.shared.b16 {%0,%1,%2,%3}, [%4];"
        : "=r"(r[0]), "=r"(r[1]), "=r"(r[2]), "=r"(r[3]) : "r"(a));
}
__device__ __forceinline__ void mma_f16(float* c, const uint32_t* a, const uint32_t* b) {
    asm volatile("mma.sync.aligned.m16n8k16.row.col.f32.f16.f16.f32 "
        "{%0,%1,%2,%3}, {%4,%5,%6,%7}, {%8,%9}, {%0,%1,%2,%3};"
        : "+f"(c[0]), "+f"(c[1]), "+f"(c[2]), "+f"(c[3])
        : "r"(a[0]), "r"(a[1]), "r"(a[2]), "r"(a[3]), "r"(b[0]), "r"(b[1]));
}
__device__ __forceinline__ void cp16(uint32_t dst, const void* src) {
    asm volatile("cp.async.cg.shared.global [%0], [%1], 16;" :: "r"(dst), "l"(src));
}
#define CP_COMMIT() asm volatile("cp.async.commit_group;" ::: "memory")
#define CP_WAIT1()  asm volatile("cp.async.wait_group 1;" ::: "memory")
#define CP_WAIT0()  asm volatile("cp.async.wait_group 0;" ::: "memory")

// SMEM byte offsets (ec kernel)
#define OFF_B2    0
#define OFF_P     512
#define OFF_ADJ   1024
#define OFF_RED   2048
#define OFF_W1HI  6144
#define OFF_W2HI  14848
#define OFF_E0    49664
#define SMEM_EC   (OFF_E0 + 2*EBYTES)   // 90624

// ---------------------------------------------------------------------------
__device__ __forceinline__ void pq_impl(int group, const float* __restrict__ x,
                                        const float* __restrict__ W1,
                                        const float* __restrict__ b1, int C_in,
                                        float* __restrict__ P, float* __restrict__ Q)
{
    __shared__ float sx[4][128];
    __shared__ float sp[2][4][128], sq[2][4][128];
    const int tid = threadIdx.x;
    const int cs = tid >> 7, h = tid & 127;
    const int base = group * 4;
    const int lg = (C_in == 64) ? 6 : 7;
    for (int i = tid; i < 4*C_in; i += 256)
        sx[i >> lg][i & (C_in-1)] = x[(size_t)(base + (i >> lg))*C_in + (i & (C_in-1))];
    __syncthreads();

    const int c0 = cs * (C_in >> 1), c1 = c0 + (C_in >> 1);
    float p[4] = {0.f,0.f,0.f,0.f}, q[4] = {0.f,0.f,0.f,0.f};
    for (int c = c0; c < c1; ++c) {
        float wa = W1[c*H_ + h], wb = W1[(C_in+c)*H_ + h], wd = wa - wb;
        #pragma unroll
        for (int r = 0; r < 4; ++r) { p[r] += sx[r][c]*wd; q[r] += sx[r][c]*wb; }
    }
    #pragma unroll
    for (int r = 0; r < 4; ++r) { sp[cs][r][h] = p[r]; sq[cs][r][h] = q[r]; }
    __syncthreads();
    if (cs == 0) {
        float bb = b1[h];
        #pragma unroll
        for (int r = 0; r < 4; ++r) {
            P[(size_t)(base+r)*H_ + h] = sp[0][r][h] + sp[1][r][h] + bb;
            Q[(size_t)(base+r)*H_ + h] = sq[0][r][h] + sq[1][r][h];
        }
    }
}

__global__ void prep_all(const float* __restrict__ E,
                         const float* __restrict__ W1a, const float* __restrict__ W2a,
                         const float* __restrict__ W1b, const float* __restrict__ W2b,
                         const float* __restrict__ x0,  const float* __restrict__ b1a,
                         float* __restrict__ P, float* __restrict__ Q)
{
    const int blk = blockIdx.x, tid = threadIdx.x;
    if (blk < NBI) {
        unsigned short* eh = g_Ehi[blk];
        for (int idx = tid; idx < 2048; idx += 256) {
            int j = idx >> 3, kq = idx & 7;
            float4 e4 = *(const float4*)(E + ((size_t)blk*V_ + j)*KE_ + kq*4);
            uint2 hp;
            hp.x = (uint32_t)f16b(e4.x) | ((uint32_t)f16b(e4.y) << 16);
            hp.y = (uint32_t)f16b(e4.z) | ((uint32_t)f16b(e4.w) << 16);
            *(uint2*)(eh + j*ST_E2 + kq*4) = hp;
        }
    } else if (blk < NBI + 160) {
        int idx = (blk - NBI) * 256 + tid;
        if (idx < 40960) {
            int layer = idx / 20480;
            int t = idx - layer * 20480;
            const float* W1 = layer ? W1b : W1a;
            const float* W2 = layer ? W2b : W2a;
            const int C = layer ? 128 : 64;
            if (t < KE_*H_) {
                int k = t >> 7, c = t & 127;
                g_w1hi[layer][k*ST_W + c] = f16b(W1[(size_t)(2*C + k)*H_ + c]);
            } else {
                int t2 = t - KE_*H_;
                int k = t2 >> 7, c = t2 & 127;
                g_w2hi[layer][k*ST_W + c] = f16b(W2[(size_t)k*H_ + c]);
            }
        }
    } else {
        pq_impl(blk - (NBI + 160), x0, W1a, b1a, 64, P, Q);
    }
}

__global__ void pq_kernel(const float* __restrict__ x, const float* __restrict__ W1,
                          const float* __restrict__ b1, int C_in,
                          float* __restrict__ P, float* __restrict__ Q)
{
    pq_impl(blockIdx.x, x, W1, b1, C_in, P, Q);
}

// ---------------------------------------------------------------------------
// Persistent-CTA fused EdgeConv, single-fp16 HMMA.
// Phase 1 + epi1 run per chunk (both chunks' T A-fragments kept in regs);
// phase 2 is COMBINED across chunks so each W2 fragment is loaded once,
// processed in two sequential n-halves to bound register pressure.
// ---------------------------------------------------------------------------
__global__ void __launch_bounds__(256, 1)
ec_hmma(const float* __restrict__ Pg, const float* __restrict__ Qg,
        const float* __restrict__ b2, const int* __restrict__ adj,
        float* __restrict__ Xout, int layer)
{
    extern __shared__ char smem[];
    const uint32_t sb = smem_to_u32(smem);
    const int tid = threadIdx.x, w = tid >> 5, lane = tid & 31;
    const int g = lane >> 2, tg = lane & 3;
    const int j0 = w * 16;
    const int rowsel = lane & 15, colsel = (lane >> 4) * 8;

    {   // stage weight tiles ONCE
        const uint4* s; uint4* d;
        s = (const uint4*)g_w1hi[layer]; d = (uint4*)(smem + OFF_W1HI);
        for (int i = tid; i < 544;  i += 256) d[i] = s[i];
        s = (const uint4*)g_w2hi[layer]; d = (uint4*)(smem + OFF_W2HI);
        for (int i = tid; i < 2176; i += 256) d[i] = s[i];
    }
    float* sPf  = (float*)(smem + OFF_P);
    float* sB2f = (float*)(smem + OFF_B2);
    int*   sAdj = (int*)(smem + OFF_ADJ);
    float* red  = (float*)(smem + OFF_RED);
    if (tid < H_) sB2f[tid] = b2[tid];

    int cur = 0;
    {
        const char* sh = (const char*)g_Ehi[blockIdx.x];
        for (int i = tid; i < EBYTES/16; i += 256)
            cp16(sb + OFF_E0 + i*16, sh + i*16);
        CP_COMMIT();
    }

    for (int bi = blockIdx.x; bi < NBI; bi += gridDim.x) {
        const int b = bi >> 8;
        const int nbi = bi + gridDim.x;
        float pv = (tid < H_) ? Pg[(size_t)bi*H_ + tid] : 0.f;
        int   av = adj[(size_t)bi*V_ + tid];
        if (nbi < NBI) {
            const int nb = 1 - cur;
            const char* sh = (const char*)g_Ehi[nbi];
            for (int i = tid; i < EBYTES/16; i += 256)
                cp16(sb + OFF_E0 + nb*EBYTES + i*16, sh + i*16);
            CP_COMMIT();
            CP_WAIT1();
        } else {
            CP_WAIT0();
        }
        if (tid < H_) sPf[tid] = pv;
        sAdj[tid] = av;
        __syncthreads();

        const uint32_t eH = sb + OFF_E0 + cur*EBYTES;

        // ---- phase 1 + epilogue 1 for BOTH chunks -> aH2[2][8][4] ----
        uint32_t aH2[2][8][4];
        #pragma unroll
        for (int chunk = 0; chunk < 2; ++chunk) {
            const int jbase = chunk * 128;
            float acc[16][4];
            #pragma unroll
            for (int n = 0; n < 16; ++n)
                #pragma unroll
                for (int p = 0; p < 4; ++p) acc[n][p] = 0.f;

            #pragma unroll
            for (int ks = 0; ks < 2; ++ks) {
                const int k0 = ks * 16;
                uint32_t aH[4];
                uint32_t ao = (uint32_t)((jbase + j0 + rowsel)*ST_E2 + k0 + colsel) * 2u;
                ldsm4(aH, eH + ao);
                const uint32_t brow = (uint32_t)((k0 + rowsel)*ST_W + colsel) * 2u;
                #pragma unroll
                for (int ntp = 0; ntp < 8; ++ntp) {
                    uint32_t bH[4];
                    ldsm4t(bH, sb + OFF_W1HI + brow + (uint32_t)(ntp*16*2));
                    mma_f16(acc[2*ntp],   aH, &bH[0]);
                    mma_f16(acc[2*ntp+1], aH, &bH[2]);
                }
            }

            // epilogue 1: T = relu(P + Q + D) -> fp16 A-fragments
            const float* qA = Qg + ((size_t)(b*V_ + jbase + j0 + g))*H_;
            const float* qB = qA + 8*H_;
            #pragma unroll
            for (int ks = 0; ks < 8; ++ks) {
                #pragma unroll
                for (int h = 0; h < 2; ++h) {
                    const int nt = 2*ks + h;
                    const int c = nt*8 + tg*2;
                    float2 q0 = *(const float2*)(qA + c);
                    float2 q1 = *(const float2*)(qB + c);
                    float pc0 = sPf[c], pc1 = sPf[c+1];
                    float t0 = fmaxf(acc[nt][0] + pc0 + q0.x, 0.f);
                    float t1 = fmaxf(acc[nt][1] + pc1 + q0.y, 0.f);
                    float t2 = fmaxf(acc[nt][2] + pc0 + q1.x, 0.f);
                    float t3 = fmaxf(acc[nt][3] + pc1 + q1.y, 0.f);
                    aH2[chunk][ks][0 + 2*h] = (uint32_t)f16b(t0) | ((uint32_t)f16b(t1) << 16);
                    aH2[chunk][ks][1 + 2*h] = (uint32_t)f16b(t2) | ((uint32_t)f16b(t3) << 16);
                }
            }
        }

        float rmax[32];
        #pragma unroll
        for (int i = 0; i < 32; ++i) rmax[i] = -1e9f;

        const bool actA0 = sAdj[j0 + g] > 0,        actB0 = sAdj[j0 + 8 + g] > 0;
        const bool actA1 = sAdj[128 + j0 + g] > 0,  actB1 = sAdj[128 + j0 + 8 + g] > 0;

        // ---- phase 2 COMBINED: each W2 fragment loaded once, two n-halves ----
        #pragma unroll
        for (int half = 0; half < 2; ++half) {
            float a0[8][4], a1[8][4];
            #pragma unroll
            for (int n = 0; n < 8; ++n)
                #pragma unroll
                for (int p = 0; p < 4; ++p) { a0[n][p] = 0.f; a1[n][p] = 0.f; }

            #pragma unroll
            for (int ks = 0; ks < 8; ++ks) {
                const uint32_t brow =
                    (uint32_t)((ks*16 + rowsel)*ST_W + half*64 + colsel) * 2u;
                #pragma unroll
                for (int ntp = 0; ntp < 4; ++ntp) {
                    uint32_t bH[4];
                    ldsm4t(bH, sb + OFF_W2HI + brow + (uint32_t)(ntp*16*2));
                    mma_f16(a0[2*ntp],   aH2[0][ks], &bH[0]);
                    mma_f16(a0[2*ntp+1], aH2[0][ks], &bH[2]);
                    mma_f16(a1[2*ntp],   aH2[1][ks], &bH[0]);
                    mma_f16(a1[2*ntp+1], aH2[1][ks], &bH[2]);
                }
            }

            // epilogue 2 for this n-half: relu(+b2), masked max (both chunks)
            #pragma unroll
            for (int nt = 0; nt < 8; ++nt) {
                const int gnt = half*8 + nt;
                const int c = gnt*8 + tg*2;
                float b0 = sB2f[c], b1 = sB2f[c+1];
                if (actA0) {
                    rmax[2*gnt]   = fmaxf(rmax[2*gnt],   fmaxf(a0[nt][0]+b0, 0.f));
                    rmax[2*gnt+1] = fmaxf(rmax[2*gnt+1], fmaxf(a0[nt][1]+b1, 0.f));
                }
                if (actB0) {
                    rmax[2*gnt]   = fmaxf(rmax[2*gnt],   fmaxf(a0[nt][2]+b0, 0.f));
                    rmax[2*gnt+1] = fmaxf(rmax[2*gnt+1], fmaxf(a0[nt][3]+b1, 0.f));
                }
                if (actA1) {
                    rmax[2*gnt]   = fmaxf(rmax[2*gnt],   fmaxf(a1[nt][0]+b0, 0.f));
                    rmax[2*gnt+1] = fmaxf(rmax[2*gnt+1], fmaxf(a1[nt][1]+b1, 0.f));
                }
                if (actB1) {
                    rmax[2*gnt]   = fmaxf(rmax[2*gnt],   fmaxf(a1[nt][2]+b0, 0.f));
                    rmax[2*gnt+1] = fmaxf(rmax[2*gnt+1], fmaxf(a1[nt][3]+b1, 0.f));
                }
            }
        }

        // reduce over g, then over warps via smem
        #pragma unroll
        for (int off = 4; off <= 16; off <<= 1)
            #pragma unroll
            for (int i = 0; i < 32; ++i)
                rmax[i] = fmaxf(rmax[i], __shfl_xor_sync(0xffffffffu, rmax[i], off));

        if (lane < 4) {
            #pragma unroll
            for (int nt = 0; nt < 16; ++nt) {
                red[w*H_ + nt*8 + lane*2]     = rmax[2*nt];
                red[w*H_ + nt*8 + lane*2 + 1] = rmax[2*nt+1];
            }
        }
        __syncthreads();
        if (tid < H_) {
            float v = red[tid];
            #pragma unroll
            for (int ww = 1; ww < 8; ++ww) v = fmaxf(v, red[ww*H_ + tid]);
            Xout[(size_t)bi*H_ + tid] = (v < -1e8f) ? 0.f : v;
        }
        __syncthreads();
        cur ^= 1;
    }
}

// ---------------------------------------------------------------------------
__global__ void __launch_bounds__(512)
rs_kernel(const float* __restrict__ x, const float* __restrict__ W3,
          const float* __restrict__ b3,
          float* __restrict__ R, float* __restrict__ S)
{
    __shared__ float sx[4][128];
    __shared__ float sr[2][4][256], ss[2][4][256];
    const int tid = threadIdx.x;
    const int cs = tid >> 8, m = tid & 255;
    const int base = blockIdx.x * 4;
    sx[tid >> 7][tid & 127] = x[(size_t)(base + (tid >> 7))*H_ + (tid & 127)];
    __syncthreads();

    const int c0 = cs * 64, c1 = c0 + 64;
    float r[4] = {0.f,0.f,0.f,0.f}, s[4] = {0.f,0.f,0.f,0.f};
    for (int c = c0; c < c1; ++c) {
        float wa = W3[c*H2_ + m], wb = W3[(128+c)*H2_ + m];
        #pragma unroll
        for (int rr = 0; rr < 4; ++rr) { r[rr] += sx[rr][c]*wa; s[rr] += sx[rr][c]*wb; }
    }
    #pragma unroll
    for (int rr = 0; rr < 4; ++rr) { sr[cs][rr][m] = r[rr]; ss[cs][rr][m] = s[rr]; }
    __syncthreads();
    if (cs == 0) {
        float bb = b3[m];
        #pragma unroll
        for (int rr = 0; rr < 4; ++rr) {
            R[(size_t)(base+rr)*H2_ + m] = sr[0][rr][m] + sr[1][rr][m];
            S[(size_t)(base+rr)*H2_ + m] = ss[0][rr][m] + ss[1][rr][m] + bb;
        }
    }
}

#define IL_ 8
#define MC_ 32
__global__ void __launch_bounds__(256)
pair_kernel(const float* __restrict__ R, const float* __restrict__ S,
            const float* __restrict__ outW, const float* __restrict__ outB,
            float* __restrict__ out)
{
    __shared__ float sR[V_][MC_+1];
    __shared__ float sS[IL_][MC_+1];
    __shared__ float sw[MC_];
    const int tid = threadIdx.x;
    const int b = blockIdx.y, i0 = blockIdx.x * IL_;
    float acc[IL_];
    #pragma unroll
    for (int il = 0; il < IL_; ++il) acc[il] = 0.f;

    for (int mc = 0; mc < H2_; mc += MC_) {
        __syncthreads();
        #pragma unroll 4
        for (int idx = tid; idx < V_*MC_; idx += 256) {
            int j = idx >> 5, mm = idx & (MC_-1);
            sR[j][mm] = R[((size_t)b*V_ + j)*H2_ + mc + mm];
        }
        if (tid < IL_*MC_) {
            int il = tid >> 5, mm = tid & (MC_-1);
            sS[il][mm] = S[((size_t)b*V_ + i0 + il)*H2_ + mc + mm];
        }
        if (tid < MC_) sw[tid] = outW[mc + tid];
        __syncthreads();
        #pragma unroll
        for (int il = 0; il < IL_; ++il) {
            float a = 0.f;
            #pragma unroll
            for (int mm = 0; mm < MC_; ++mm)
                a += fmaxf(sR[tid][mm] + sS[il][mm], 0.f) * sw[mm];
            acc[il] += a;
        }
    }
    const float ob = outB[0];
    #pragma unroll
    for (int il = 0; il < IL_; ++il) {
        float z = acc[il] + ob;
        out[((size_t)b*V_ + i0 + il)*V_ + tid] = 1.f / (1.f + expf(-z));
    }
}

// ---------------------------------------------------------------------------
extern "C" void kernel_launch(void* const* d_in, const int* in_sizes, int n_in,
                              void* d_out, int out_size)
{
    const int*   adj   = (const int*)  d_in[0];
    const float* x0    = (const float*)d_in[1];
    const float* e     = (const float*)d_in[2];
    const float* ec1W1 = (const float*)d_in[3];
    const float* ec1b1 = (const float*)d_in[4];
    const float* ec1W2 = (const float*)d_in[5];
    const float* ec1b2 = (const float*)d_in[6];
    const float* ec2W1 = (const float*)d_in[7];
    const float* ec2b1 = (const float*)d_in[8];
    const float* ec2W2 = (const float*)d_in[9];
    const float* ec2b2 = (const float*)d_in[10];
    const float* h3W   = (const float*)d_in[11];
    const float* h3b   = (const float*)d_in[12];
    const float* outW  = (const float*)d_in[13];
    const float* outB  = (const float*)d_in[14];
    float* out = (float*)d_out;

    float *P, *Q, *X1, *X2, *R, *S;
    cudaGetSymbolAddress((void**)&P,  g_P);
    cudaGetSymbolAddress((void**)&Q,  g_Q);
    cudaGetSymbolAddress((void**)&X1, g_X1);
    cudaGetSymbolAddress((void**)&X2, g_X2);
    cudaGetSymbolAddress((void**)&R,  g_R);
    cudaGetSymbolAddress((void**)&S,  g_S);

    cudaFuncSetAttribute(ec_hmma, cudaFuncAttributeMaxDynamicSharedMemorySize, SMEM_EC);

    int sms = 148;
    cudaDeviceGetAttribute(&sms, cudaDevAttrMultiProcessorCount, 0);
    int grid = sms < NBI ? sms : NBI;

    prep_all<<<NBI + 160 + 256, 256>>>(e, ec1W1, ec1W2, ec2W1, ec2W2, x0, ec1b1, P, Q);

    ec_hmma<<<grid, 256, SMEM_EC>>>(P, Q, ec1b2, adj, X1, 0);

    pq_kernel<<<NBI/4, 256>>>(X1, ec2W1, ec2b1, 128, P, Q);
    ec_hmma<<<grid, 256, SMEM_EC>>>(P, Q, ec2b2, adj, X2, 1);

    rs_kernel<<<NBI/4, 512>>>(X2, h3W, h3b, R, S);
    dim3 pg(V_/IL_, B_);
    pair_kernel<<<pg, 256>>>(R, S, outW, outB, out);
}